// round 16
// baseline (speedup 1.0000x reference)
#include <cuda_runtime.h>
#include <cstdint>

#define BATCHN 4096
#define INSZ   1024
#define HUN    512
#define GN     2048
#define SHID   4096
#define OHID   2048

#define BK     32                      // f32 per K-chunk
#define NSTAGE 3
#define APLANE 516                     // u32 stride per 16B-plane (A: 128 rows*4 + 4 skew)
#define BPLANE 260                     // u32 stride per 16B-plane (B: 64 rows*4 + 4 skew)
#define ATILE_U (8*APLANE)             // 4128 u32
#define BTILE_U (8*BPLANE)             // 2080 u32
#define STGU   (ATILE_U+BTILE_U)       // 6208 u32 = 24832 B per stage
#define SMEM_BYTES (NSTAGE*STGU*4)     // 74496 B -> 3 CTAs/SM (223.5KB)

// Scratch (device globals: allocation-free)
__device__ float g_h0[(size_t)4 * BATCHN * HUN];
__device__ float g_X2[(size_t)4 * BATCHN * INSZ];

__device__ __forceinline__ void cp16(uint32_t s, const void* g) {
    asm volatile("cp.async.cg.shared.global [%0], [%1], 16;\n" :: "r"(s), "l"(g));
}
__device__ __forceinline__ void cpcommit() { asm volatile("cp.async.commit_group;\n" ::: "memory"); }
template <int N> __device__ __forceinline__ void cpwait() {
    asm volatile("cp.async.wait_group %0;\n" :: "n"(N) : "memory");
}
__device__ __forceinline__ void ldsm4(uint32_t* r, uint32_t addr) {
    asm volatile("ldmatrix.sync.aligned.m8n8.x4.shared.b16 {%0,%1,%2,%3}, [%4];\n"
                 : "=r"(r[0]), "=r"(r[1]), "=r"(r[2]), "=r"(r[3]) : "r"(addr));
}
__device__ __forceinline__ void mma8(float* c, const uint32_t* a, const uint32_t* b) {
    asm volatile(
        "mma.sync.aligned.m16n8k8.row.col.f32.tf32.tf32.f32 "
        "{%0,%1,%2,%3}, {%4,%5,%6,%7}, {%8,%9}, {%0,%1,%2,%3};\n"
        : "+f"(c[0]), "+f"(c[1]), "+f"(c[2]), "+f"(c[3])
        : "r"(a[0]), "r"(a[1]), "r"(a[2]), "r"(a[3]), "r"(b[0]), "r"(b[1]));
}
__device__ __forceinline__ float sigm(float x) { return 1.f / (1.f + __expf(-x)); }

// 8 warps as 4(M) x 2(N); warp tile 32 x 32. acc[2][4][4] = 32 regs.
// k-outer smem layout: chunk (row, g16) at g16*PLANE + row*4 u32.
__device__ __forceinline__ void compute_stage(uint32_t sA, uint32_t sB,
                                              int wm, int wn, int lane,
                                              float acc[2][4][4])
{
    const int q = lane >> 3, jj = lane & 7;
    #pragma unroll
    for (int ks = 0; ks < 4; ks++) {
        uint32_t a[2][4], b[2][4];
        #pragma unroll
        for (int mt = 0; mt < 2; mt++) {
            // quads: q0:(rows+0,k+0) q1:(rows+8,k+0) q2:(rows+0,k+4) q3:(rows+8,k+4)
            int r = wm * 32 + mt * 16 + (q & 1) * 8 + jj;
            int g = ks * 2 + (q >> 1);
            ldsm4(a[mt], sA + (uint32_t)(g * APLANE + r * 4) * 4);
        }
        #pragma unroll
        for (int nt = 0; nt < 2; nt++) {
            // quads: q0:(cols+0,k+0) q1:(cols+0,k+4) q2:(cols+8,k+0) q3:(cols+8,k+4)
            int c = wn * 32 + nt * 16 + (q >> 1) * 8 + jj;
            int g = ks * 2 + (q & 1);
            ldsm4(b[nt], sB + (uint32_t)(g * BPLANE + c * 4) * 4);
        }
        #pragma unroll
        for (int mt = 0; mt < 2; mt++)
            #pragma unroll
            for (int nt = 0; nt < 2; nt++) {
                mma8(acc[mt][2 * nt],     a[mt], &b[nt][0]);
                mma8(acc[mt][2 * nt + 1], a[mt], &b[nt][2]);
            }
    }
}

// ---------------------------------------------------------------------------
// gates kernel: 128 rows x (4 gates x 16 hidden) per CTA, (depth d, stack j).
// GEMM: [X | hx] @ [Wih | Whh]^T, K = 1536.
// ---------------------------------------------------------------------------
__global__ __launch_bounds__(256, 3) void gates_kernel(
    const float* __restrict__ input, const float* __restrict__ state,
    const float* __restrict__ Wih, const float* __restrict__ Whh,
    const float* __restrict__ bih, const float* __restrict__ bhh,
    int j, float* __restrict__ out_ho, float* __restrict__ out_state)
{
    extern __shared__ uint32_t dynsmem[];
    const uint32_t smbase = (uint32_t)__cvta_generic_to_shared(dynsmem);

    const int tid  = threadIdx.x;
    const int lane = tid & 31;
    const int wid  = tid >> 5;
    const int wm   = wid >> 1;      // 0..3
    const int wn   = wid & 1;       // 0..1
    const int d    = blockIdx.z;
    const int m0   = blockIdx.y * 128;
    const int hblk = blockIdx.x;    // 0..31 -> 16 hidden units

    const float* X   = (j == 0) ? input : (g_X2 + (size_t)d * BATCHN * INSZ);
    const float* Wi  = Wih + (size_t)(d * 2 + j) * GN * INSZ;
    const float* Wh  = Whh + (size_t)(d * 2 + j) * GN * HUN;
    const float* hxb = state + (size_t)j * BATCHN * SHID + (size_t)d * HUN;

    // Thread -> base chunk (row rr, 16B-chunk qq); u advances rows by +32.
    const int rr = tid >> 3, qq = tid & 7;
    const float* srcAX = X   + (size_t)(m0 + rr) * INSZ + qq * 4;
    const float* srcAH = hxb + (size_t)(m0 + rr) * SHID + qq * 4;
    const uint32_t dstA = smbase + (uint32_t)(qq * APLANE + rr * 4) * 4;
    const int wr0 = (rr >> 4) * HUN + hblk * 16 + (rr & 15);   // gathered gate row
    const float* srcBX = Wi + (size_t)wr0 * INSZ + qq * 4;
    const float* srcBH = Wh + (size_t)wr0 * HUN + qq * 4;
    const uint32_t dstB = smbase + (uint32_t)(ATILE_U + qq * BPLANE + rr * 4) * 4;

    auto load_stage = [&](int kt, int s) {
        const uint32_t so = (uint32_t)(s * STGU * 4);
        const int k0 = kt * BK;
        if (k0 < INSZ) {
            #pragma unroll
            for (int u = 0; u < 4; u++)        // A rows rr, rr+32, rr+64, rr+96
                cp16(dstA + so + u * 512, srcAX + k0 + (size_t)u * 32 * INSZ);
            #pragma unroll
            for (int u = 0; u < 2; u++)        // B rows rr, rr+32 (+2 gates = +1024 W rows)
                cp16(dstB + so + u * 512, srcBX + k0 + (size_t)u * 1024 * INSZ);
        } else {
            const int kh = k0 - INSZ;
            #pragma unroll
            for (int u = 0; u < 4; u++)
                cp16(dstA + so + u * 512, srcAH + kh + (size_t)u * 32 * SHID);
            #pragma unroll
            for (int u = 0; u < 2; u++)
                cp16(dstB + so + u * 512, srcBH + kh + (size_t)u * 1024 * HUN);
        }
    };

    float acc[2][4][4];
    #pragma unroll
    for (int a = 0; a < 2; a++)
        #pragma unroll
        for (int b = 0; b < 4; b++)
            #pragma unroll
            for (int c = 0; c < 4; c++) acc[a][b][c] = 0.f;

    const int NT = 1536 / BK;   // 48
    load_stage(0, 0); cpcommit();
    load_stage(1, 1); cpcommit();

    #pragma unroll 1
    for (int kt = 0; kt < NT; kt++) {
        __syncthreads();          // all warps done with stage (kt-1) = slot being refilled
        const int kn = kt + 2;
        if (kn < NT) load_stage(kn, kn % NSTAGE);
        cpcommit();               // unconditional: ledger stays consistent
        cpwait<2>();              // stage kt resident (overlapped with barrier+issue)
        const uint32_t sA = smbase + (uint32_t)((kt % NSTAGE) * STGU * 4);
        compute_stage(sA, sA + ATILE_U * 4, wm, wn, lane, acc);
    }
    __syncthreads();

    // Scatter accumulators to smem C tile [128][68]
    float* Csm = (float*)dynsmem;
    const int gid = lane >> 2, t4 = lane & 3;
    #pragma unroll
    for (int mt = 0; mt < 2; mt++)
        #pragma unroll
        for (int nt = 0; nt < 4; nt++) {
            int r = wm * 32 + mt * 16 + gid;
            int c = wn * 32 + nt * 8 + 2 * t4;
            Csm[r * 68 + c]           = acc[mt][nt][0];
            Csm[r * 68 + c + 1]       = acc[mt][nt][1];
            Csm[(r + 8) * 68 + c]     = acc[mt][nt][2];
            Csm[(r + 8) * 68 + c + 1] = acc[mt][nt][3];
        }
    __syncthreads();

    // LSTM epilogue: 128 rows x 16 hidden; 8 (m,h) pairs per thread.
    const int hl = tid & 15;
    const int hg = hblk * 16 + hl;
    const size_t bb = (size_t)(d * 2 + j) * GN;
    const float bi0 = bih[bb + hg]           + bhh[bb + hg];
    const float bf0 = bih[bb + HUN + hg]     + bhh[bb + HUN + hg];
    const float bg0 = bih[bb + 2 * HUN + hg] + bhh[bb + 2 * HUN + hg];
    const float bo0 = bih[bb + 3 * HUN + hg] + bhh[bb + 3 * HUN + hg];
    const int colO = d * HUN + hg;

    #pragma unroll 4
    for (int p = 0; p < 8; p++) {
        const int idx = p * 256 + tid;
        const int m = idx >> 4;
        const int row = m0 + m;

        float gi = Csm[m * 68 + hl]      + bi0;
        float gf = Csm[m * 68 + 16 + hl] + bf0;
        float gg = Csm[m * 68 + 32 + hl] + bg0;
        float go = Csm[m * 68 + 48 + hl] + bo0;

        float i_ = sigm(gi), f_ = sigm(gf), g_ = tanhf(gg), o_ = sigm(go);

        float cx = state[((size_t)(2 + j) * BATCHN + row) * SHID + colO];
        float cn = f_ * cx + i_ * g_;
        float hn = o_ * tanhf(cn);
        float hx = state[((size_t)j * BATCHN + row) * SHID + colO];
        float hs = hn + hx;

        if (out_state) {
            out_state[((size_t)j * BATCHN + row) * OHID + colO] = hs;
            out_state[((size_t)(2 + j) * BATCHN + row) * OHID + colO] = cn;
        }
        if (j == 1) {
            if (out_ho) out_ho[(size_t)row * OHID + colO] = hs;
        } else {
            g_h0[((size_t)d * BATCHN + row) * HUN + hg] = hn;
        }
    }
}

// ---------------------------------------------------------------------------
// proj kernel: X2[d] = input + h0[d] @ projW^T + projb  (M=4096, N=1024, K=512)
// ---------------------------------------------------------------------------
__global__ __launch_bounds__(256, 3) void proj_kernel(
    const float* __restrict__ projW, const float* __restrict__ projb,
    const float* __restrict__ input)
{
    extern __shared__ uint32_t dynsmem[];
    const uint32_t smbase = (uint32_t)__cvta_generic_to_shared(dynsmem);

    const int tid  = threadIdx.x;
    const int lane = tid & 31;
    const int wid  = tid >> 5;
    const int wm   = wid >> 1;
    const int wn   = wid & 1;
    const int d    = blockIdx.z;
    const int m0   = blockIdx.y * 128;
    const int nblk = blockIdx.x;     // 0..15 -> 64 output cols

    const float* A = g_h0 + (size_t)d * BATCHN * HUN;

    const int rr = tid >> 3, qq = tid & 7;
    const float* srcA = A + (size_t)(m0 + rr) * HUN + qq * 4;
    const uint32_t dstA = smbase + (uint32_t)(qq * APLANE + rr * 4) * 4;
    const float* srcB = projW + (size_t)(nblk * 64 + rr) * HUN + qq * 4;
    const uint32_t dstB = smbase + (uint32_t)(ATILE_U + qq * BPLANE + rr * 4) * 4;

    auto load_stage = [&](int kt, int s) {
        const uint32_t so = (uint32_t)(s * STGU * 4);
        const int k0 = kt * BK;
        #pragma unroll
        for (int u = 0; u < 4; u++)
            cp16(dstA + so + u * 512, srcA + k0 + (size_t)u * 32 * HUN);
        #pragma unroll
        for (int u = 0; u < 2; u++)
            cp16(dstB + so + u * 512, srcB + k0 + (size_t)u * 32 * HUN);
    };

    float acc[2][4][4];
    #pragma unroll
    for (int a = 0; a < 2; a++)
        #pragma unroll
        for (int b = 0; b < 4; b++)
            #pragma unroll
            for (int c = 0; c < 4; c++) acc[a][b][c] = 0.f;

    const int NT = 512 / BK;   // 16
    load_stage(0, 0); cpcommit();
    load_stage(1, 1); cpcommit();

    #pragma unroll 1
    for (int kt = 0; kt < NT; kt++) {
        __syncthreads();
        const int kn = kt + 2;
        if (kn < NT) load_stage(kn, kn % NSTAGE);
        cpcommit();
        cpwait<2>();
        const uint32_t sA = smbase + (uint32_t)((kt % NSTAGE) * STGU * 4);
        compute_stage(sA, sA + ATILE_U * 4, wm, wn, lane, acc);
    }
    __syncthreads();

    float* Csm = (float*)dynsmem;
    const int gid = lane >> 2, t4 = lane & 3;
    #pragma unroll
    for (int mt = 0; mt < 2; mt++)
        #pragma unroll
        for (int nt = 0; nt < 4; nt++) {
            int r = wm * 32 + mt * 16 + gid;
            int c = wn * 32 + nt * 8 + 2 * t4;
            Csm[r * 68 + c]           = acc[mt][nt][0];
            Csm[r * 68 + c + 1]       = acc[mt][nt][1];
            Csm[(r + 8) * 68 + c]     = acc[mt][nt][2];
            Csm[(r + 8) * 68 + c + 1] = acc[mt][nt][3];
        }
    __syncthreads();

    const int cl  = tid & 63;
    const int col = nblk * 64 + cl;
    const float pb = projb[col];
    #pragma unroll 4
    for (int p = 0; p < 32; p++) {
        const int idx = p * 256 + tid;
        const int m = idx >> 6;
        const int row = m0 + m;
        float v = Csm[m * 68 + cl] + pb + input[(size_t)row * INSZ + col];
        g_X2[((size_t)d * BATCHN + row) * INSZ + col] = v;
    }
}

extern "C" void kernel_launch(void* const* d_in, const int* in_sizes, int n_in,
                              void* d_out, int out_size)
{
    const float* input = (const float*)d_in[0];
    const float* state = (const float*)d_in[1];
    const float* Wih   = (const float*)d_in[2];
    const float* Whh   = (const float*)d_in[3];
    const float* bih   = (const float*)d_in[4];
    const float* bhh   = (const float*)d_in[5];
    const float* projW = (const float*)d_in[6];
    const float* projb = (const float*)d_in[7];

    float* out = (float*)d_out;
    const size_t HO_ELEMS = (size_t)BATCHN * OHID;
    const size_t ST_ELEMS = (size_t)4 * BATCHN * OHID;

    float* out_ho = nullptr;
    float* out_state = nullptr;
    if ((size_t)out_size >= HO_ELEMS + ST_ELEMS) {
        out_ho = out;
        out_state = out + HO_ELEMS;
    } else if ((size_t)out_size == ST_ELEMS) {
        out_state = out;
    } else {
        out_ho = out;
    }

    cudaFuncSetAttribute(gates_kernel, cudaFuncAttributeMaxDynamicSharedMemorySize, SMEM_BYTES);
    cudaFuncSetAttribute(proj_kernel,  cudaFuncAttributeMaxDynamicSharedMemorySize, SMEM_BYTES);

    dim3 blk(256);
    gates_kernel<<<dim3(32, 32, 4), blk, SMEM_BYTES>>>(input, state, Wih, Whh, bih, bhh,
                                                       0, out_ho, out_state);
    proj_kernel<<<dim3(16, 32, 4), blk, SMEM_BYTES>>>(projW, projb, input);
    gates_kernel<<<dim3(32, 32, 4), blk, SMEM_BYTES>>>(input, state, Wih, Whh, bih, bhh,
                                                       1, out_ho, out_state);
}